// round 1
// baseline (speedup 1.0000x reference)
#include <cuda_runtime.h>
#include <cuda_bf16.h>
#include <math.h>

// DeformableSpatialAttention: fused pipeline
//   K1: channel mean+max reduce  x(8,256,128,128) -> g_att(8,2,128,128)
//   K2: per row-block: 7x7 conv (2->147ch, f32x2 FMA) + mask sigmoid
//       + deformable sampling + sigmoid -> g_attmap(8,128,128)
//   K3: out = x * attmap (broadcast over channels)

#define Bn   8
#define Cn   256
#define Hn   128
#define Wn   128
#define HW   (Hn*Wn)       // 16384
#define KK   49
#define NOFF 98
#define NCH  147
#define NCHP 160           // padded channel count (16 groups x 10)
#define NTAP 98            // 2 in-channels * 49 taps

typedef unsigned long long ull;

__device__ float g_att[Bn*2*HW];    // [b][c][y][x]
__device__ float g_attmap[Bn*HW];   // [b][y][x]

// ---------- f32x2 helpers (Blackwell packed fp32) ----------
__device__ __forceinline__ ull pack2(float lo, float hi){
    ull r;
    asm("mov.b64 %0, {%1,%2};" : "=l"(r)
        : "r"(__float_as_uint(lo)), "r"(__float_as_uint(hi)));
    return r;
}
__device__ __forceinline__ ull fma2(ull a, ull b, ull c){
    ull d;
    asm("fma.rn.f32x2 %0, %1, %2, %3;" : "=l"(d) : "l"(a), "l"(b), "l"(c));
    return d;
}
__device__ __forceinline__ float2 unpack2(ull v){
    unsigned lo, hi;
    asm("mov.b64 {%0,%1}, %2;" : "=r"(lo), "=r"(hi) : "l"(v));
    return make_float2(__uint_as_float(lo), __uint_as_float(hi));
}

// ================= K1: channel reduce =================
__global__ void dsa_reduce_kernel(const float* __restrict__ x){
    int p   = blockIdx.x * 256 + threadIdx.x;   // 0..131071
    int b   = p >> 14;
    int pix = p & 16383;
    const float* base = x + (b << 22) + pix;    // b*256*16384 + pix
    float s = 0.f, mx = -1e30f;
    #pragma unroll 8
    for (int c = 0; c < Cn; c++){
        float v = base[c << 14];
        s += v;
        mx = fmaxf(mx, v);
    }
    g_att[(b << 15) + pix]         = s * (1.f/256.f);
    g_att[(b << 15) + HW + pix]    = mx;
}

// ================= K2: fused conv + deform =================
// SMEM layout (bytes)
#define SM_W2    0                        // 98*160 ull (dup weights)   125440
#define SM_CONV  125440                   // 160*128 float               81920
#define SM_ATT   207360                   // 2*7*136 float                7616
#define SM_BIAS  214976                   // 160 float                     640
#define SM_DW    215616                   // 98 float (+pad)               400
#define SM_PART  216016                   // 512 float                    2048
#define SM_TOTAL 218064

__device__ __forceinline__ void bilin2(const float* __restrict__ i0,
                                       const float* __restrict__ i1,
                                       float py, float px,
                                       float& s0, float& s1){
    float fy = floorf(py), fx = floorf(px);
    int y0 = (int)fy, x0 = (int)fx;
    int y1 = y0 + 1,  x1 = x0 + 1;
    float wy1 = py - fy, wy0 = 1.f - wy1;
    float wx1 = px - fx, wx0 = 1.f - wx1;
    float w00 = wy0*wx0, w01 = wy0*wx1, w10 = wy1*wx0, w11 = wy1*wx1;
    s0 = 0.f; s1 = 0.f;
    bool yv0 = (unsigned)y0 < (unsigned)Hn, yv1 = (unsigned)y1 < (unsigned)Hn;
    bool xv0 = (unsigned)x0 < (unsigned)Wn, xv1 = (unsigned)x1 < (unsigned)Wn;
    if (yv0 && xv0){ int o = (y0<<7)+x0; s0 += w00*i0[o]; s1 += w00*i1[o]; }
    if (yv0 && xv1){ int o = (y0<<7)+x1; s0 += w01*i0[o]; s1 += w01*i1[o]; }
    if (yv1 && xv0){ int o = (y1<<7)+x0; s0 += w10*i0[o]; s1 += w10*i1[o]; }
    if (yv1 && xv1){ int o = (y1<<7)+x1; s0 += w11*i0[o]; s1 += w11*i1[o]; }
}

__global__ __launch_bounds__(512, 1)
void dsa_conv_deform_kernel(const float* __restrict__ offset_w,
                            const float* __restrict__ offset_b,
                            const float* __restrict__ mod_w,
                            const float* __restrict__ mod_b,
                            const float* __restrict__ dconv_w){
    extern __shared__ char smraw[];
    ull*   w2    = (ull*)  (smraw + SM_W2);     // [tap][NCHP] duplicated pairs
    float* convs = (float*)(smraw + SM_CONV);   // [NCHP][128]
    float* atts  = (float*)(smraw + SM_ATT);    // [2][7][136]
    float* biass = (float*)(smraw + SM_BIAS);
    float* dws   = (float*)(smraw + SM_DW);
    float* parts = (float*)(smraw + SM_PART);

    const int tid = threadIdx.x;
    const int b   = blockIdx.x >> 7;
    const int y   = blockIdx.x & 127;

    // ---- stage weights (duplicated for f32x2), biases, halo ----
    for (int i = tid; i < NTAP*NCHP; i += 512){
        int t  = i / NCHP;
        int ch = i - t*NCHP;
        float w = 0.f;
        if      (ch < NOFF) w = offset_w[ch*NTAP + t];
        else if (ch < NCH)  w = mod_w[(ch-NOFF)*NTAP + t];
        w2[i] = pack2(w, w);
    }
    if (tid < NCHP)
        biass[tid] = (tid < NOFF) ? offset_b[tid]
                   : (tid < NCH)  ? mod_b[tid-NOFF] : 0.f;
    if (tid < NTAP) dws[tid] = dconv_w[tid];

    for (int i = tid; i < 2*7*136; i += 512){
        int c   = i / (7*136);
        int rem = i - c*7*136;
        int r   = rem / 136;
        int cx  = rem - r*136;
        int gy  = y + r - 3;
        int gx  = cx - 3;
        float v = 0.f;
        if ((unsigned)gy < (unsigned)Hn && (unsigned)gx < (unsigned)Wn)
            v = g_att[((b*2 + c) << 14) + (gy << 7) + gx];
        atts[i] = v;
    }
    __syncthreads();

    // ---- conv: each thread = 10 channels x 2 pixel-pairs ----
    const int lane   = tid & 31;
    const int tg     = tid >> 5;        // 0..15
    const int chBase = tg * 10;
    const int x0     = lane * 2;        // pairA pixels x0,x0+1 ; pairB +64

    ull accA[10], accB[10];
    #pragma unroll
    for (int k = 0; k < 10; k++){ accA[k] = 0ull; accB[k] = 0ull; }

    #pragma unroll 1
    for (int c = 0; c < 2; c++){
        #pragma unroll 1
        for (int dy = 0; dy < 7; dy++){
            const float* row = atts + (c*7 + dy)*136;
            const ull*   wt  = w2 + (c*49 + dy*7)*NCHP + chBase;
            #pragma unroll
            for (int dx = 0; dx < 7; dx++){
                ull aA = pack2(row[x0+dx],      row[x0+dx+1]);
                ull aB = pack2(row[x0+64+dx],   row[x0+64+dx+1]);
                const ull* w = wt + dx*NCHP;
                #pragma unroll
                for (int k = 0; k < 10; k++){
                    ull ww = w[k];
                    accA[k] = fma2(aA, ww, accA[k]);
                    accB[k] = fma2(aB, ww, accB[k]);
                }
            }
        }
    }

    // ---- epilogue: bias, mask sigmoid, stage into SMEM ----
    #pragma unroll
    for (int k = 0; k < 10; k++){
        int ch = chBase + k;
        float bias = biass[ch];
        float2 fa = unpack2(accA[k]);
        float2 fb = unpack2(accB[k]);
        float v0 = fa.x + bias, v1 = fa.y + bias;
        float v2 = fb.x + bias, v3 = fb.y + bias;
        if (ch >= NOFF){   // modulation mask = 2*sigmoid(conv)
            v0 = 2.f/(1.f+expf(-v0)); v1 = 2.f/(1.f+expf(-v1));
            v2 = 2.f/(1.f+expf(-v2)); v3 = 2.f/(1.f+expf(-v3));
        }
        float* crow = convs + ch*Wn;
        crow[x0]    = v0; crow[x0+1]  = v1;
        crow[x0+64] = v2; crow[x0+65] = v3;
    }
    __syncthreads();

    // ---- deformable sampling: 4 ways x 128 pixels ----
    {
        const int way = tid >> 7;       // 0..3
        const int px  = tid & 127;
        const float* i0 = g_att + ((b*2 + 0) << 14);
        const float* i1 = g_att + ((b*2 + 1) << 14);
        float part = 0.f;
        for (int kk = way; kk < KK; kk += 4){
            float oy = convs[(2*kk  )*Wn + px];
            float ox = convs[(2*kk+1)*Wn + px];
            float m  = convs[(NOFF+kk)*Wn + px];
            float py = (float)(y + kk/7 - 3) + oy;
            float pxx= (float)(px + kk%7 - 3) + ox;
            float s0, s1;
            bilin2(i0, i1, py, pxx, s0, s1);
            part += (s0*dws[kk] + s1*dws[KK+kk]) * m;
        }
        parts[way*128 + px] = part;
    }
    __syncthreads();

    if (tid < 128){
        float d = parts[tid] + parts[128+tid] + parts[256+tid] + parts[384+tid];
        g_attmap[(b << 14) + (y << 7) + tid] = 1.f/(1.f + expf(-d));
    }
}

// ================= K3: out = x * attmap =================
__global__ void dsa_mul_kernel(const float* __restrict__ x,
                               float* __restrict__ out){
    int gid = blockIdx.x * 256 + threadIdx.x;       // float4 index
    float4 xv = ((const float4*)x)[gid];
    int e   = gid << 2;
    int b   = e >> 22;          // 256*16384 per batch
    int pix = e & 16383;
    float4 a = *(const float4*)(g_attmap + (b << 14) + pix);
    xv.x *= a.x; xv.y *= a.y; xv.z *= a.z; xv.w *= a.w;
    ((float4*)out)[gid] = xv;
}

// ================= launch =================
extern "C" void kernel_launch(void* const* d_in, const int* in_sizes, int n_in,
                              void* d_out, int out_size){
    const float* x        = (const float*)d_in[0];
    const float* offset_w = (const float*)d_in[1];
    const float* offset_b = (const float*)d_in[2];
    const float* mod_w    = (const float*)d_in[3];
    const float* mod_b    = (const float*)d_in[4];
    const float* dconv_w  = (const float*)d_in[5];
    float* out = (float*)d_out;

    cudaFuncSetAttribute(dsa_conv_deform_kernel,
                         cudaFuncAttributeMaxDynamicSharedMemorySize, SM_TOTAL);

    dsa_reduce_kernel<<<(Bn*HW)/256, 256>>>(x);
    dsa_conv_deform_kernel<<<Bn*Hn, 512, SM_TOTAL>>>(offset_w, offset_b,
                                                     mod_w, mod_b, dconv_w);
    dsa_mul_kernel<<<(Bn*Cn*HW/4)/256, 256>>>(x, out);
}

// round 2
// speedup vs baseline: 1.0007x; 1.0007x over previous
#include <cuda_runtime.h>
#include <cuda_bf16.h>
#include <math.h>

// DeformableSpatialAttention: fused pipeline
//   K1: channel mean+max reduce  x(8,256,128,128) -> g_att(8,2,128,128)
//   K2: per row-block: 7x7 conv (2->147ch, f32x2 FMA) + mask sigmoid
//       + deformable sampling + sigmoid -> g_attmap(8,128,128)
//   K3: out = x * attmap (broadcast over channels)

#define Bn   8
#define Cn   256
#define Hn   128
#define Wn   128
#define HW   (Hn*Wn)       // 16384
#define KK   49
#define NOFF 98
#define NCH  147
#define NCHP 160           // padded channel count (16 groups x 10)
#define NTAP 98            // 2 in-channels * 49 taps

typedef unsigned long long ull;

__device__ float g_att[Bn*2*HW];    // [b][c][y][x]
__device__ float g_attmap[Bn*HW];   // [b][y][x]

// ---------- f32x2 helpers (Blackwell packed fp32) ----------
__device__ __forceinline__ ull pack2(float lo, float hi){
    ull r;
    asm("mov.b64 %0, {%1,%2};" : "=l"(r)
        : "r"(__float_as_uint(lo)), "r"(__float_as_uint(hi)));
    return r;
}
__device__ __forceinline__ ull fma2(ull a, ull b, ull c){
    ull d;
    asm("fma.rn.f32x2 %0, %1, %2, %3;" : "=l"(d) : "l"(a), "l"(b), "l"(c));
    return d;
}
__device__ __forceinline__ float2 unpack2(ull v){
    unsigned lo, hi;
    asm("mov.b64 {%0,%1}, %2;" : "=r"(lo), "=r"(hi) : "l"(v));
    return make_float2(__uint_as_float(lo), __uint_as_float(hi));
}

// ================= K1: channel reduce =================
__global__ void dsa_reduce_kernel(const float* __restrict__ x){
    int p   = blockIdx.x * 256 + threadIdx.x;   // 0..131071
    int b   = p >> 14;
    int pix = p & 16383;
    const float* base = x + (b << 22) + pix;    // b*256*16384 + pix
    float s = 0.f, mx = -1e30f;
    #pragma unroll 8
    for (int c = 0; c < Cn; c++){
        float v = base[c << 14];
        s += v;
        mx = fmaxf(mx, v);
    }
    g_att[(b << 15) + pix]         = s * (1.f/256.f);
    g_att[(b << 15) + HW + pix]    = mx;
}

// ================= K2: fused conv + deform =================
// SMEM layout (bytes)
#define SM_W2    0                        // 98*160 ull (dup weights)   125440
#define SM_CONV  125440                   // 160*128 float               81920
#define SM_ATT   207360                   // 2*7*136 float                7616
#define SM_BIAS  214976                   // 160 float                     640
#define SM_DW    215616                   // 98 float (+pad)               400
#define SM_PART  216016                   // 512 float                    2048
#define SM_TOTAL 218064

__device__ __forceinline__ void bilin2(const float* __restrict__ i0,
                                       const float* __restrict__ i1,
                                       float py, float px,
                                       float& s0, float& s1){
    float fy = floorf(py), fx = floorf(px);
    int y0 = (int)fy, x0 = (int)fx;
    int y1 = y0 + 1,  x1 = x0 + 1;
    float wy1 = py - fy, wy0 = 1.f - wy1;
    float wx1 = px - fx, wx0 = 1.f - wx1;
    float w00 = wy0*wx0, w01 = wy0*wx1, w10 = wy1*wx0, w11 = wy1*wx1;
    s0 = 0.f; s1 = 0.f;
    bool yv0 = (unsigned)y0 < (unsigned)Hn, yv1 = (unsigned)y1 < (unsigned)Hn;
    bool xv0 = (unsigned)x0 < (unsigned)Wn, xv1 = (unsigned)x1 < (unsigned)Wn;
    if (yv0 && xv0){ int o = (y0<<7)+x0; s0 += w00*i0[o]; s1 += w00*i1[o]; }
    if (yv0 && xv1){ int o = (y0<<7)+x1; s0 += w01*i0[o]; s1 += w01*i1[o]; }
    if (yv1 && xv0){ int o = (y1<<7)+x0; s0 += w10*i0[o]; s1 += w10*i1[o]; }
    if (yv1 && xv1){ int o = (y1<<7)+x1; s0 += w11*i0[o]; s1 += w11*i1[o]; }
}

__global__ __launch_bounds__(512, 1)
void dsa_conv_deform_kernel(const float* __restrict__ offset_w,
                            const float* __restrict__ offset_b,
                            const float* __restrict__ mod_w,
                            const float* __restrict__ mod_b,
                            const float* __restrict__ dconv_w){
    extern __shared__ char smraw[];
    ull*   w2    = (ull*)  (smraw + SM_W2);     // [tap][NCHP] duplicated pairs
    float* convs = (float*)(smraw + SM_CONV);   // [NCHP][128]
    float* atts  = (float*)(smraw + SM_ATT);    // [2][7][136]
    float* biass = (float*)(smraw + SM_BIAS);
    float* dws   = (float*)(smraw + SM_DW);
    float* parts = (float*)(smraw + SM_PART);

    const int tid = threadIdx.x;
    const int b   = blockIdx.x >> 7;
    const int y   = blockIdx.x & 127;

    // ---- stage weights (duplicated for f32x2), biases, halo ----
    for (int i = tid; i < NTAP*NCHP; i += 512){
        int t  = i / NCHP;
        int ch = i - t*NCHP;
        float w = 0.f;
        if      (ch < NOFF) w = offset_w[ch*NTAP + t];
        else if (ch < NCH)  w = mod_w[(ch-NOFF)*NTAP + t];
        w2[i] = pack2(w, w);
    }
    if (tid < NCHP)
        biass[tid] = (tid < NOFF) ? offset_b[tid]
                   : (tid < NCH)  ? mod_b[tid-NOFF] : 0.f;
    if (tid < NTAP) dws[tid] = dconv_w[tid];

    for (int i = tid; i < 2*7*136; i += 512){
        int c   = i / (7*136);
        int rem = i - c*7*136;
        int r   = rem / 136;
        int cx  = rem - r*136;
        int gy  = y + r - 3;
        int gx  = cx - 3;
        float v = 0.f;
        if ((unsigned)gy < (unsigned)Hn && (unsigned)gx < (unsigned)Wn)
            v = g_att[((b*2 + c) << 14) + (gy << 7) + gx];
        atts[i] = v;
    }
    __syncthreads();

    // ---- conv: each thread = 10 channels x 2 pixel-pairs ----
    const int lane   = tid & 31;
    const int tg     = tid >> 5;        // 0..15
    const int chBase = tg * 10;
    const int x0     = lane * 2;        // pairA pixels x0,x0+1 ; pairB +64

    ull accA[10], accB[10];
    #pragma unroll
    for (int k = 0; k < 10; k++){ accA[k] = 0ull; accB[k] = 0ull; }

    #pragma unroll 1
    for (int c = 0; c < 2; c++){
        #pragma unroll 1
        for (int dy = 0; dy < 7; dy++){
            const float* row = atts + (c*7 + dy)*136;
            const ull*   wt  = w2 + (c*49 + dy*7)*NCHP + chBase;
            #pragma unroll
            for (int dx = 0; dx < 7; dx++){
                ull aA = pack2(row[x0+dx],      row[x0+dx+1]);
                ull aB = pack2(row[x0+64+dx],   row[x0+64+dx+1]);
                const ull* w = wt + dx*NCHP;
                #pragma unroll
                for (int k = 0; k < 10; k++){
                    ull ww = w[k];
                    accA[k] = fma2(aA, ww, accA[k]);
                    accB[k] = fma2(aB, ww, accB[k]);
                }
            }
        }
    }

    // ---- epilogue: bias, mask sigmoid, stage into SMEM ----
    #pragma unroll
    for (int k = 0; k < 10; k++){
        int ch = chBase + k;
        float bias = biass[ch];
        float2 fa = unpack2(accA[k]);
        float2 fb = unpack2(accB[k]);
        float v0 = fa.x + bias, v1 = fa.y + bias;
        float v2 = fb.x + bias, v3 = fb.y + bias;
        if (ch >= NOFF){   // modulation mask = 2*sigmoid(conv)
            v0 = 2.f/(1.f+expf(-v0)); v1 = 2.f/(1.f+expf(-v1));
            v2 = 2.f/(1.f+expf(-v2)); v3 = 2.f/(1.f+expf(-v3));
        }
        float* crow = convs + ch*Wn;
        crow[x0]    = v0; crow[x0+1]  = v1;
        crow[x0+64] = v2; crow[x0+65] = v3;
    }
    __syncthreads();

    // ---- deformable sampling: 4 ways x 128 pixels ----
    {
        const int way = tid >> 7;       // 0..3
        const int px  = tid & 127;
        const float* i0 = g_att + ((b*2 + 0) << 14);
        const float* i1 = g_att + ((b*2 + 1) << 14);
        float part = 0.f;
        for (int kk = way; kk < KK; kk += 4){
            float oy = convs[(2*kk  )*Wn + px];
            float ox = convs[(2*kk+1)*Wn + px];
            float m  = convs[(NOFF+kk)*Wn + px];
            float py = (float)(y + kk/7 - 3) + oy;
            float pxx= (float)(px + kk%7 - 3) + ox;
            float s0, s1;
            bilin2(i0, i1, py, pxx, s0, s1);
            part += (s0*dws[kk] + s1*dws[KK+kk]) * m;
        }
        parts[way*128 + px] = part;
    }
    __syncthreads();

    if (tid < 128){
        float d = parts[tid] + parts[128+tid] + parts[256+tid] + parts[384+tid];
        g_attmap[(b << 14) + (y << 7) + tid] = 1.f/(1.f + expf(-d));
    }
}

// ================= K3: out = x * attmap =================
__global__ void dsa_mul_kernel(const float* __restrict__ x,
                               float* __restrict__ out){
    int gid = blockIdx.x * 256 + threadIdx.x;       // float4 index
    float4 xv = ((const float4*)x)[gid];
    int e   = gid << 2;
    int b   = e >> 22;          // 256*16384 per batch
    int pix = e & 16383;
    float4 a = *(const float4*)(g_attmap + (b << 14) + pix);
    xv.x *= a.x; xv.y *= a.y; xv.z *= a.z; xv.w *= a.w;
    ((float4*)out)[gid] = xv;
}

// ================= launch =================
extern "C" void kernel_launch(void* const* d_in, const int* in_sizes, int n_in,
                              void* d_out, int out_size){
    const float* x        = (const float*)d_in[0];
    const float* offset_w = (const float*)d_in[1];
    const float* offset_b = (const float*)d_in[2];
    const float* mod_w    = (const float*)d_in[3];
    const float* mod_b    = (const float*)d_in[4];
    const float* dconv_w  = (const float*)d_in[5];
    float* out = (float*)d_out;

    cudaFuncSetAttribute(dsa_conv_deform_kernel,
                         cudaFuncAttributeMaxDynamicSharedMemorySize, SM_TOTAL);

    dsa_reduce_kernel<<<(Bn*HW)/256, 256>>>(x);
    dsa_conv_deform_kernel<<<Bn*Hn, 512, SM_TOTAL>>>(offset_w, offset_b,
                                                     mod_w, mod_b, dconv_w);
    dsa_mul_kernel<<<(Bn*Cn*HW/4)/256, 256>>>(x, out);
}

// round 5
// speedup vs baseline: 1.3753x; 1.3744x over previous
#include <cuda_runtime.h>
#include <cuda_bf16.h>
#include <math.h>
#include <stdint.h>

// DeformableSpatialAttention — tf32 mma.sync conv edition (baseline PTX only;
// harness lowers to .target sm_100, so no tcgen05/arch-'a' features).
//   K0: pad + tf32-round conv weights -> g_wBp[160][108]; biases -> g_bias
//   K1: channel mean+max reduce (float4) -> g_att(8,2,128,128)
//   K2: per image-row: im2col A[128][108] -> warp mma.sync tf32 GEMM
//       (128x160x104) -> bias/mask-sigmoid -> deformable sampling -> attmap
//   K3: out = x * attmap

#define Bn   8
#define Cn   256
#define Hn   128
#define Wn   128
#define HW   (Hn*Wn)
#define KK   49
#define NOFF 98
#define NCH  147
#define NP   160          // padded N (channels)
#define KM   104          // padded K (13 * 8)
#define KS   108          // SMEM k-stride (bank-conflict-free padding)
#define CS   132          // conv staging px-stride

__device__ float g_att[Bn*2*HW];
__device__ float g_attmap[Bn*HW];
__device__ __align__(16) float g_wBp[NP*KS];   // padded, tf32-rounded weights
__device__ float g_bias[NP];

__device__ __forceinline__ float tf32r(float v){
    uint32_t r;
    asm("cvt.rna.tf32.f32 %0, %1;" : "=r"(r) : "f"(v));
    return __uint_as_float(r);
}

// ================= K0: weight prep =================
__global__ void dsa_prep_kernel(const float* __restrict__ ow, const float* __restrict__ ob,
                                const float* __restrict__ mw, const float* __restrict__ mb){
    int stride = gridDim.x * blockDim.x;
    for (int i = blockIdx.x*blockDim.x + threadIdx.x; i < NP*KS; i += stride){
        int n = i / KS;
        int k = i - n*KS;
        float v = 0.f;
        if (k < NOFF){
            if      (n < NOFF) v = ow[n*NOFF + k];
            else if (n < NCH)  v = mw[(n-NOFF)*NOFF + k];
        }
        g_wBp[i] = tf32r(v);
        if (k == 0)
            g_bias[n] = (n < NOFF) ? ob[n] : (n < NCH) ? mb[n-NOFF] : 0.f;
    }
}

// ================= K1: channel reduce (float4) =================
__global__ void dsa_reduce_kernel(const float* __restrict__ x){
    int t  = blockIdx.x * 256 + threadIdx.x;
    int b  = t >> 12;
    int p4 = t & 4095;
    const float4* base = (const float4*)x + (size_t)b*(Cn*HW/4) + p4;
    float4 s = make_float4(0.f,0.f,0.f,0.f);
    float4 m = make_float4(-1e30f,-1e30f,-1e30f,-1e30f);
    #pragma unroll 8
    for (int c = 0; c < Cn; c++){
        float4 v = base[c*(HW/4)];
        s.x += v.x; s.y += v.y; s.z += v.z; s.w += v.w;
        m.x = fmaxf(m.x, v.x); m.y = fmaxf(m.y, v.y);
        m.z = fmaxf(m.z, v.z); m.w = fmaxf(m.w, v.w);
    }
    const float r = 1.f/256.f;
    float4 sm4 = make_float4(s.x*r, s.y*r, s.z*r, s.w*r);
    ((float4*)g_att)[b*(2*HW/4) + p4]        = sm4;
    ((float4*)g_att)[b*(2*HW/4) + HW/4 + p4] = m;
}

// ================= K2: mma.sync tf32 conv + deform =================
// SMEM layout (bytes)
#define SM_A     0                 // 128*108*4 = 55296
#define SM_B     55296             // 160*108*4 = 69120 -> 124416
#define SM_ATT   124416            // 2*7*136*4 = 7616 -> pad 7680 -> 132096
#define SM_BIAS  132096            // 160*4 = 640 -> 132736
#define SM_DW    132736            // 98*4 -> pad 512 -> 133248
#define SM_PART  133248            // 512*4 = 2048 -> 135296
#define SM_TOTAL 135296
#define SM_CONV  0                 // overlay: 147*132*4 = 77616 (A+B dead)

__device__ __forceinline__ void bilin2(const float* __restrict__ i0,
                                       const float* __restrict__ i1,
                                       float py, float px,
                                       float& s0, float& s1){
    float fy = floorf(py), fx = floorf(px);
    int y0 = (int)fy, x0 = (int)fx;
    int y1 = y0 + 1,  x1 = x0 + 1;
    float wy1 = py - fy, wy0 = 1.f - wy1;
    float wx1 = px - fx, wx0 = 1.f - wx1;
    float w00 = wy0*wx0, w01 = wy0*wx1, w10 = wy1*wx0, w11 = wy1*wx1;
    s0 = 0.f; s1 = 0.f;
    bool yv0 = (unsigned)y0 < (unsigned)Hn, yv1 = (unsigned)y1 < (unsigned)Hn;
    bool xv0 = (unsigned)x0 < (unsigned)Wn, xv1 = (unsigned)x1 < (unsigned)Wn;
    if (yv0 && xv0){ int o = (y0<<7)+x0; s0 += w00*i0[o]; s1 += w00*i1[o]; }
    if (yv0 && xv1){ int o = (y0<<7)+x1; s0 += w01*i0[o]; s1 += w01*i1[o]; }
    if (yv1 && xv0){ int o = (y1<<7)+x0; s0 += w10*i0[o]; s1 += w10*i1[o]; }
    if (yv1 && xv1){ int o = (y1<<7)+x1; s0 += w11*i0[o]; s1 += w11*i1[o]; }
}

__global__ __launch_bounds__(512)
void dsa_conv_deform_kernel(const float* __restrict__ dconv_w){
    extern __shared__ char sm[];
    float* As    = (float*)(sm + SM_A);
    float* Bs    = (float*)(sm + SM_B);
    float* atts  = (float*)(sm + SM_ATT);
    float* biass = (float*)(sm + SM_BIAS);
    float* dws   = (float*)(sm + SM_DW);
    float* parts = (float*)(sm + SM_PART);
    float* convs = (float*)(sm + SM_CONV);

    const int tid  = threadIdx.x;
    const int wid  = tid >> 5;
    const int lane = tid & 31;
    const int g    = lane >> 2;      // groupID (0..7)
    const int tig  = lane & 3;       // thread-in-group (0..3)
    const int b    = blockIdx.x >> 7;
    const int y    = blockIdx.x & 127;

    // ---- stage halo atts[2][7][136] ----
    for (int i = tid; i < 2*7*136; i += 512){
        int c   = i / (7*136);
        int rem = i - c*7*136;
        int r   = rem / 136;
        int cx  = rem - r*136;
        int gy  = y + r - 3;
        int gx  = cx - 3;
        float v = 0.f;
        if ((unsigned)gy < (unsigned)Hn && (unsigned)gx < (unsigned)Wn)
            v = g_att[((b*2 + c) << 14) + (gy << 7) + gx];
        atts[i] = v;
    }
    // ---- copy padded weights B ----
    {
        const float4* src = (const float4*)g_wBp;
        float4* dst = (float4*)Bs;
        #pragma unroll 3
        for (int i = tid; i < (NP*KS)/4; i += 512) dst[i] = src[i];
    }
    if (tid < NP)   biass[tid] = g_bias[tid];
    if (tid < 2*KK) dws[tid]   = dconv_w[tid];
    __syncthreads();

    // ---- build im2col A [128 px][108 k] (tf32-rounded) ----
    for (int i = tid; i < 128*KM; i += 512){
        int k  = i >> 7;
        int px = i & 127;
        float v = 0.f;
        if (k < NOFF){
            int c  = (k >= KK) ? 1 : 0;
            int r  = k - c*KK;
            int dy = r / 7;
            int dx = r - dy*7;
            v = tf32r(atts[(c*7 + dy)*136 + px + dx]);
        }
        As[px*KS + k] = v;
    }
    __syncthreads();

    // ---- warp GEMM: 16 warps, each 32(M) x 40(N), K=104 ----
    const int mrow = (wid & 3) * 32;
    const int ncol = (wid >> 2) * 40;

    float acc[2][5][4];
    #pragma unroll
    for (int mi = 0; mi < 2; mi++)
        #pragma unroll
        for (int ni = 0; ni < 5; ni++)
            #pragma unroll
            for (int j = 0; j < 4; j++) acc[mi][ni][j] = 0.f;

    #pragma unroll
    for (int ks = 0; ks < 13; ks++){
        const int k = ks*8;
        uint32_t a[2][4];
        #pragma unroll
        for (int mi = 0; mi < 2; mi++){
            const int m0 = mrow + mi*16;
            const float* ap = As + k + tig;
            a[mi][0] = __float_as_uint(ap[(m0+g  )*KS    ]);
            a[mi][1] = __float_as_uint(ap[(m0+8+g)*KS    ]);
            a[mi][2] = __float_as_uint(ap[(m0+g  )*KS + 4]);
            a[mi][3] = __float_as_uint(ap[(m0+8+g)*KS + 4]);
        }
        #pragma unroll
        for (int ni = 0; ni < 5; ni++){
            const int n0 = ncol + ni*8;
            uint32_t b0 = __float_as_uint(Bs[(n0+g)*KS + k + tig    ]);
            uint32_t b1 = __float_as_uint(Bs[(n0+g)*KS + k + tig + 4]);
            #pragma unroll
            for (int mi = 0; mi < 2; mi++){
                asm volatile(
                    "mma.sync.aligned.m16n8k8.row.col.f32.tf32.tf32.f32 "
                    "{%0,%1,%2,%3}, {%4,%5,%6,%7}, {%8,%9}, {%0,%1,%2,%3};"
                    : "+f"(acc[mi][ni][0]), "+f"(acc[mi][ni][1]),
                      "+f"(acc[mi][ni][2]), "+f"(acc[mi][ni][3])
                    : "r"(a[mi][0]), "r"(a[mi][1]), "r"(a[mi][2]), "r"(a[mi][3]),
                      "r"(b0), "r"(b1));
            }
        }
    }
    __syncthreads();   // A/B reads complete; overlay with conv staging

    // ---- epilogue: bias + mask sigmoid, stage convs[ch][px] (stride 132) ----
    #pragma unroll
    for (int mi = 0; mi < 2; mi++){
        const int m0 = mrow + mi*16;
        #pragma unroll
        for (int ni = 0; ni < 5; ni++){
            const int n0 = ncol + ni*8 + 2*tig;
            #pragma unroll
            for (int j = 0; j < 4; j++){
                int ch = n0 + (j & 1);
                int px = m0 + g + ((j >> 1) << 3);
                if (ch < NCH){
                    float v = acc[mi][ni][j] + biass[ch];
                    if (ch >= NOFF) v = 2.f/(1.f + expf(-v));
                    convs[ch*CS + px] = v;
                }
            }
        }
    }
    __syncthreads();

    // ---- deformable sampling: 4 ways x 128 px ----
    {
        const int way = tid >> 7;
        const int px  = tid & 127;
        const float* i0 = g_att + ((b*2 + 0) << 14);
        const float* i1 = g_att + ((b*2 + 1) << 14);
        float part = 0.f;
        for (int kk = way; kk < KK; kk += 4){
            float oy = convs[(2*kk  )*CS + px];
            float ox = convs[(2*kk+1)*CS + px];
            float mk = convs[(NOFF+kk)*CS + px];
            float py = (float)(y + kk/7 - 3) + oy;
            float pxx= (float)(px + kk%7 - 3) + ox;
            float s0, s1;
            bilin2(i0, i1, py, pxx, s0, s1);
            part += (s0*dws[kk] + s1*dws[KK+kk]) * mk;
        }
        parts[way*128 + px] = part;
    }
    __syncthreads();

    if (tid < 128){
        float d = parts[tid] + parts[128+tid] + parts[256+tid] + parts[384+tid];
        g_attmap[(b << 14) + (y << 7) + tid] = 1.f/(1.f + expf(-d));
    }
}

// ================= K3: out = x * attmap =================
__global__ void dsa_mul_kernel(const float* __restrict__ x,
                               float* __restrict__ out){
    int gid = blockIdx.x * 256 + threadIdx.x;       // float4 index
    float4 xv = ((const float4*)x)[gid];
    int e   = gid << 2;
    int b   = e >> 22;
    int pix = e & 16383;
    float4 a = *(const float4*)(g_attmap + (b << 14) + pix);
    xv.x *= a.x; xv.y *= a.y; xv.z *= a.z; xv.w *= a.w;
    ((float4*)out)[gid] = xv;
}

// ================= launch =================
extern "C" void kernel_launch(void* const* d_in, const int* in_sizes, int n_in,
                              void* d_out, int out_size){
    const float* x        = (const float*)d_in[0];
    const float* offset_w = (const float*)d_in[1];
    const float* offset_b = (const float*)d_in[2];
    const float* mod_w    = (const float*)d_in[3];
    const float* mod_b    = (const float*)d_in[4];
    const float* dconv_w  = (const float*)d_in[5];
    float* out = (float*)d_out;

    cudaFuncSetAttribute(dsa_conv_deform_kernel,
                         cudaFuncAttributeMaxDynamicSharedMemorySize, SM_TOTAL);

    dsa_prep_kernel<<<16, 512>>>(offset_w, offset_b, mod_w, mod_b);
    dsa_reduce_kernel<<<128, 256>>>(x);
    dsa_conv_deform_kernel<<<Bn*Hn, 512, SM_TOTAL>>>(dconv_w);
    dsa_mul_kernel<<<(Bn*Cn*HW/4)/256, 256>>>(x, out);
}

// round 6
// speedup vs baseline: 1.4375x; 1.0452x over previous
#include <cuda_runtime.h>
#include <cuda_bf16.h>
#include <math.h>
#include <stdint.h>

// DeformableSpatialAttention — tf32 mma.sync, low-SMEM 2-blocks/SM edition
//   K0: pad + tf32-round conv weights -> g_wBp[160][108]; biases -> g_bias
//   K1: channel mean+max reduce (float4, streaming) -> g_att(8,2,128,128)
//   K2: per image-row: im2col A[128][108] direct from g_att -> warp mma.sync
//       tf32 GEMM (128x160x104, B fragments via __ldg/L1) -> bias/mask-sigmoid
//       -> deformable sampling -> attmap.  SMEM 81KB => 2 blocks/SM.
//   K3: out = x * attmap (streaming)

#define Bn   8
#define Cn   256
#define Hn   128
#define Wn   128
#define HW   (Hn*Wn)
#define KK   49
#define NOFF 98
#define NCH  147
#define NP   160          // padded N (channels)
#define KM   104          // padded K (13 * 8)
#define KS   108          // global/SMEM k-stride (conflict-free: 108 mod 32 = 12)
#define CS   132          // conv staging px-stride (conflict-free epilogue)

__device__ float g_att[Bn*2*HW];
__device__ float g_attmap[Bn*HW];
__device__ __align__(16) float g_wBp[NP*KS];   // padded, tf32-rounded weights
__device__ float g_bias[NP];

__device__ __forceinline__ float tf32r(float v){
    uint32_t r;
    asm("cvt.rna.tf32.f32 %0, %1;" : "=r"(r) : "f"(v));
    return __uint_as_float(r);
}

// ================= K0: weight prep =================
__global__ void dsa_prep_kernel(const float* __restrict__ ow, const float* __restrict__ ob,
                                const float* __restrict__ mw, const float* __restrict__ mb){
    int stride = gridDim.x * blockDim.x;
    for (int i = blockIdx.x*blockDim.x + threadIdx.x; i < NP*KS; i += stride){
        int n = i / KS;
        int k = i - n*KS;
        float v = 0.f;
        if (k < NOFF){
            if      (n < NOFF) v = ow[n*NOFF + k];
            else if (n < NCH)  v = mw[(n-NOFF)*NOFF + k];
        }
        g_wBp[i] = tf32r(v);
        if (k == 0)
            g_bias[n] = (n < NOFF) ? ob[n] : (n < NCH) ? mb[n-NOFF] : 0.f;
    }
}

// ================= K1: channel reduce (float4, streaming) =================
__global__ void dsa_reduce_kernel(const float* __restrict__ x){
    int t  = blockIdx.x * 256 + threadIdx.x;
    int b  = t >> 12;
    int p4 = t & 4095;
    const float4* base = (const float4*)x + (size_t)b*(Cn*HW/4) + p4;
    float4 s = make_float4(0.f,0.f,0.f,0.f);
    float4 m = make_float4(-1e30f,-1e30f,-1e30f,-1e30f);
    #pragma unroll 8
    for (int c = 0; c < Cn; c++){
        float4 v = __ldcs(base + c*(HW/4));
        s.x += v.x; s.y += v.y; s.z += v.z; s.w += v.w;
        m.x = fmaxf(m.x, v.x); m.y = fmaxf(m.y, v.y);
        m.z = fmaxf(m.z, v.z); m.w = fmaxf(m.w, v.w);
    }
    const float r = 1.f/256.f;
    float4 sm4 = make_float4(s.x*r, s.y*r, s.z*r, s.w*r);
    ((float4*)g_att)[b*(2*HW/4) + p4]        = sm4;
    ((float4*)g_att)[b*(2*HW/4) + HW/4 + p4] = m;
}

// ================= K2: mma.sync tf32 conv + deform =================
// SMEM layout (bytes): A overlaid by conv staging (A dead after GEMM)
#define SM_A     0                 // 128*108*4 = 55296
#define SM_CONV  0                 // overlay: 147*132*4 = 77616 -> pad 77824
#define SM_BIAS  77824             // 160*4 = 640
#define SM_DW    78464             // 98*4 -> pad 512
#define SM_PART  78976             // 512*4 = 2048
#define SM_TOTAL 81024

__device__ __forceinline__ void bilin2(const float* __restrict__ i0,
                                       const float* __restrict__ i1,
                                       float py, float px,
                                       float& s0, float& s1){
    float fy = floorf(py), fx = floorf(px);
    int y0 = (int)fy, x0 = (int)fx;
    int y1 = y0 + 1,  x1 = x0 + 1;
    float wy1 = py - fy, wy0 = 1.f - wy1;
    float wx1 = px - fx, wx0 = 1.f - wx1;
    float w00 = wy0*wx0, w01 = wy0*wx1, w10 = wy1*wx0, w11 = wy1*wx1;
    s0 = 0.f; s1 = 0.f;
    bool yv0 = (unsigned)y0 < (unsigned)Hn, yv1 = (unsigned)y1 < (unsigned)Hn;
    bool xv0 = (unsigned)x0 < (unsigned)Wn, xv1 = (unsigned)x1 < (unsigned)Wn;
    if (yv0 && xv0){ int o = (y0<<7)+x0; s0 += w00*i0[o]; s1 += w00*i1[o]; }
    if (yv0 && xv1){ int o = (y0<<7)+x1; s0 += w01*i0[o]; s1 += w01*i1[o]; }
    if (yv1 && xv0){ int o = (y1<<7)+x0; s0 += w10*i0[o]; s1 += w10*i1[o]; }
    if (yv1 && xv1){ int o = (y1<<7)+x1; s0 += w11*i0[o]; s1 += w11*i1[o]; }
}

__global__ __launch_bounds__(512, 2)
void dsa_conv_deform_kernel(const float* __restrict__ dconv_w){
    extern __shared__ char sm[];
    float* As    = (float*)(sm + SM_A);
    float* convs = (float*)(sm + SM_CONV);
    float* biass = (float*)(sm + SM_BIAS);
    float* dws   = (float*)(sm + SM_DW);
    float* parts = (float*)(sm + SM_PART);

    const int tid  = threadIdx.x;
    const int wid  = tid >> 5;
    const int lane = tid & 31;
    const int g    = lane >> 2;      // groupID (0..7)
    const int tig  = lane & 3;       // thread-in-group (0..3)
    const int b    = blockIdx.x >> 7;
    const int y    = blockIdx.x & 127;

    const float* att0 = g_att + ((b*2 + 0) << 14);
    const float* att1 = g_att + ((b*2 + 1) << 14);

    // ---- build im2col A [128 px][108 k] straight from g_att (L1-cached) ----
    {
        const int px = tid & 127;               // fixed per thread
        #pragma unroll
        for (int it = 0; it < 26; it++){
            int k = (tid >> 7) + it*4;          // k strides by 4
            float v = 0.f;
            if (k < NOFF){
                int c  = (k >= KK) ? 1 : 0;
                int r  = k - c*KK;
                int dy = r / 7;
                int dx = r - dy*7;
                int gy = y + dy - 3;
                int gx = px + dx - 3;
                if ((unsigned)gy < (unsigned)Hn && (unsigned)gx < (unsigned)Wn){
                    const float* src = c ? att1 : att0;
                    v = tf32r(__ldg(src + (gy << 7) + gx));
                }
            }
            As[px*KS + k] = v;
        }
    }
    if (tid < NP)   biass[tid] = g_bias[tid];
    if (tid < 2*KK) dws[tid]   = dconv_w[tid];
    __syncthreads();

    // ---- warp GEMM: 16 warps, each 32(M) x 40(N), K=104; B via __ldg/L1 ----
    const int mrow = (wid & 3) * 32;
    const int ncol = (wid >> 2) * 40;

    float acc[2][5][4];
    #pragma unroll
    for (int mi = 0; mi < 2; mi++)
        #pragma unroll
        for (int ni = 0; ni < 5; ni++)
            #pragma unroll
            for (int j = 0; j < 4; j++) acc[mi][ni][j] = 0.f;

    #pragma unroll
    for (int ks = 0; ks < 13; ks++){
        const int k = ks*8;
        uint32_t a[2][4];
        #pragma unroll
        for (int mi = 0; mi < 2; mi++){
            const int m0 = mrow + mi*16;
            const float* ap = As + k + tig;
            a[mi][0] = __float_as_uint(ap[(m0+g  )*KS    ]);
            a[mi][1] = __float_as_uint(ap[(m0+8+g)*KS    ]);
            a[mi][2] = __float_as_uint(ap[(m0+g  )*KS + 4]);
            a[mi][3] = __float_as_uint(ap[(m0+8+g)*KS + 4]);
        }
        #pragma unroll
        for (int ni = 0; ni < 5; ni++){
            const int n0 = ncol + ni*8;
            const float* bp = g_wBp + (n0+g)*KS + k + tig;
            uint32_t b0 = __float_as_uint(__ldg(bp    ));
            uint32_t b1 = __float_as_uint(__ldg(bp + 4));
            #pragma unroll
            for (int mi = 0; mi < 2; mi++){
                asm volatile(
                    "mma.sync.aligned.m16n8k8.row.col.f32.tf32.tf32.f32 "
                    "{%0,%1,%2,%3}, {%4,%5,%6,%7}, {%8,%9}, {%0,%1,%2,%3};"
                    : "+f"(acc[mi][ni][0]), "+f"(acc[mi][ni][1]),
                      "+f"(acc[mi][ni][2]), "+f"(acc[mi][ni][3])
                    : "r"(a[mi][0]), "r"(a[mi][1]), "r"(a[mi][2]), "r"(a[mi][3]),
                      "r"(b0), "r"(b1));
            }
        }
    }
    __syncthreads();   // A reads complete; overlay with conv staging

    // ---- epilogue: bias + mask sigmoid, stage convs[ch][px] (stride 132) ----
    #pragma unroll
    for (int mi = 0; mi < 2; mi++){
        const int m0 = mrow + mi*16;
        #pragma unroll
        for (int ni = 0; ni < 5; ni++){
            const int n0 = ncol + ni*8 + 2*tig;
            #pragma unroll
            for (int j = 0; j < 4; j++){
                int ch = n0 + (j & 1);
                int px = m0 + g + ((j >> 1) << 3);
                if (ch < NCH){
                    float v = acc[mi][ni][j] + biass[ch];
                    if (ch >= NOFF) v = 2.f/(1.f + expf(-v));
                    convs[ch*CS + px] = v;
                }
            }
        }
    }
    __syncthreads();

    // ---- deformable sampling: 4 ways x 128 px (unroll 2 for MLP) ----
    {
        const int way = tid >> 7;
        const int px  = tid & 127;
        float part = 0.f;
        #pragma unroll 2
        for (int kk = way; kk < KK; kk += 4){
            float oy = convs[(2*kk  )*CS + px];
            float ox = convs[(2*kk+1)*CS + px];
            float mk = convs[(NOFF+kk)*CS + px];
            float py = (float)(y + kk/7 - 3) + oy;
            float pxx= (float)(px + kk%7 - 3) + ox;
            float s0, s1;
            bilin2(att0, att1, py, pxx, s0, s1);
            part += (s0*dws[kk] + s1*dws[KK+kk]) * mk;
        }
        parts[way*128 + px] = part;
    }
    __syncthreads();

    if (tid < 128){
        float d = parts[tid] + parts[128+tid] + parts[256+tid] + parts[384+tid];
        g_attmap[(b << 14) + (y << 7) + tid] = 1.f/(1.f + expf(-d));
    }
}

// ================= K3: out = x * attmap (streaming) =================
__global__ void dsa_mul_kernel(const float* __restrict__ x,
                               float* __restrict__ out){
    int gid = blockIdx.x * 256 + threadIdx.x;       // float4 index
    float4 xv = __ldcs((const float4*)x + gid);
    int e   = gid << 2;
    int b   = e >> 22;
    int pix = e & 16383;
    float4 a = *(const float4*)(g_attmap + (b << 14) + pix);
    xv.x *= a.x; xv.y *= a.y; xv.z *= a.z; xv.w *= a.w;
    __stcs((float4*)out + gid, xv);
}

// ================= launch =================
extern "C" void kernel_launch(void* const* d_in, const int* in_sizes, int n_in,
                              void* d_out, int out_size){
    const float* x        = (const float*)d_in[0];
    const float* offset_w = (const float*)d_in[1];
    const float* offset_b = (const float*)d_in[2];
    const float* mod_w    = (const float*)d_in[3];
    const float* mod_b    = (const float*)d_in[4];
    const float* dconv_w  = (const float*)d_in[5];
    float* out = (float*)d_out;

    cudaFuncSetAttribute(dsa_conv_deform_kernel,
                         cudaFuncAttributeMaxDynamicSharedMemorySize, SM_TOTAL);

    dsa_prep_kernel<<<16, 512>>>(offset_w, offset_b, mod_w, mod_b);
    dsa_reduce_kernel<<<128, 256>>>(x);
    dsa_conv_deform_kernel<<<Bn*Hn, 512, SM_TOTAL>>>(dconv_w);
    dsa_mul_kernel<<<(Bn*Cn*HW/4)/256, 256>>>(x, out);
}

// round 7
// speedup vs baseline: 1.6884x; 1.1746x over previous
#include <cuda_runtime.h>
#include <cuda_bf16.h>
#include <cuda_fp16.h>
#include <math.h>
#include <stdint.h>

// DeformableSpatialAttention — fp16 mma.sync, spill-free 2-blocks/SM edition
//   K0: pad + fp16 conv weights -> g_wBh[160][120]; biases -> g_bias
//   K1: channel mean+max reduce (float4, streaming) -> g_att(8,2,128,128)
//   K2: per image-row: im2col A(half)[128][120] -> warp mma.sync fp16 GEMM
//       (128x160x112, 2 N-passes, 20 accs/thread) -> bias/mask-sigmoid
//       -> deformable sampling -> attmap.  SMEM 111.5KB, <=64 regs => 2 blk/SM.
//   K3: out = x * attmap (streaming)

#define Bn   8
#define Cn   256
#define Hn   128
#define Wn   128
#define HW   (Hn*Wn)
#define KK   49
#define NOFF 98
#define NCH  147
#define NP   160          // padded N (channels)
#define KM2  112          // padded K (7 * 16)
#define KS2  120          // k-stride in halves (240B rows: conflict-free frags)
#define CS   132          // conv staging px-stride

__device__ float g_att[Bn*2*HW];
__device__ float g_attmap[Bn*HW];
__device__ __align__(16) __half g_wBh[NP*KS2];   // padded fp16 weights [n][k]
__device__ float g_bias[NP];

// ================= K0: weight prep =================
__global__ void dsa_prep_kernel(const float* __restrict__ ow, const float* __restrict__ ob,
                                const float* __restrict__ mw, const float* __restrict__ mb){
    int stride = gridDim.x * blockDim.x;
    for (int i = blockIdx.x*blockDim.x + threadIdx.x; i < NP*KS2; i += stride){
        int n = i / KS2;
        int k = i - n*KS2;
        float v = 0.f;
        if (k < NOFF){
            if      (n < NOFF) v = ow[n*NOFF + k];
            else if (n < NCH)  v = mw[(n-NOFF)*NOFF + k];
        }
        g_wBh[i] = __float2half_rn(v);
        if (k == 0)
            g_bias[n] = (n < NOFF) ? ob[n] : (n < NCH) ? mb[n-NOFF] : 0.f;
    }
}

// ================= K1: channel reduce (float4, streaming) =================
__global__ void dsa_reduce_kernel(const float* __restrict__ x){
    int t  = blockIdx.x * 256 + threadIdx.x;
    int b  = t >> 12;
    int p4 = t & 4095;
    const float4* base = (const float4*)x + (size_t)b*(Cn*HW/4) + p4;
    float4 s = make_float4(0.f,0.f,0.f,0.f);
    float4 m = make_float4(-1e30f,-1e30f,-1e30f,-1e30f);
    #pragma unroll 8
    for (int c = 0; c < Cn; c++){
        float4 v = __ldcs(base + c*(HW/4));
        s.x += v.x; s.y += v.y; s.z += v.z; s.w += v.w;
        m.x = fmaxf(m.x, v.x); m.y = fmaxf(m.y, v.y);
        m.z = fmaxf(m.z, v.z); m.w = fmaxf(m.w, v.w);
    }
    const float r = 1.f/256.f;
    float4 sm4 = make_float4(s.x*r, s.y*r, s.z*r, s.w*r);
    ((float4*)g_att)[b*(2*HW/4) + p4]        = sm4;
    ((float4*)g_att)[b*(2*HW/4) + HW/4 + p4] = m;
}

// ================= K2: fp16 mma.sync conv + deform =================
// SMEM layout (bytes)
#define SM_A     0                 // 128*120*2 = 30720 (half)
#define SM_CONV  30720             // 147*132*4 = 77616 -> pad to 77680
#define SM_BIAS  108400            // 160*4 = 640
#define SM_DW    109040            // 98*4 -> pad 512
#define SM_PART  109552            // 512*4 = 2048
#define SM_TOTAL 111600

__device__ __forceinline__ void bilin2(const float* __restrict__ i0,
                                       const float* __restrict__ i1,
                                       float py, float px,
                                       float& s0, float& s1){
    float fy = floorf(py), fx = floorf(px);
    int y0 = (int)fy, x0 = (int)fx;
    int y1 = y0 + 1,  x1 = x0 + 1;
    float wy1 = py - fy, wy0 = 1.f - wy1;
    float wx1 = px - fx, wx0 = 1.f - wx1;
    float w00 = wy0*wx0, w01 = wy0*wx1, w10 = wy1*wx0, w11 = wy1*wx1;
    s0 = 0.f; s1 = 0.f;
    bool yv0 = (unsigned)y0 < (unsigned)Hn, yv1 = (unsigned)y1 < (unsigned)Hn;
    bool xv0 = (unsigned)x0 < (unsigned)Wn, xv1 = (unsigned)x1 < (unsigned)Wn;
    if (yv0 && xv0){ int o = (y0<<7)+x0; s0 += w00*i0[o]; s1 += w00*i1[o]; }
    if (yv0 && xv1){ int o = (y0<<7)+x1; s0 += w01*i0[o]; s1 += w01*i1[o]; }
    if (yv1 && xv0){ int o = (y1<<7)+x0; s0 += w10*i0[o]; s1 += w10*i1[o]; }
    if (yv1 && xv1){ int o = (y1<<7)+x1; s0 += w11*i0[o]; s1 += w11*i1[o]; }
}

__global__ __launch_bounds__(512, 2)
void dsa_conv_deform_kernel(const float* __restrict__ dconv_w){
    extern __shared__ char sm[];
    __half* Ash  = (__half*)(sm + SM_A);
    float* convs = (float*)(sm + SM_CONV);
    float* biass = (float*)(sm + SM_BIAS);
    float* dws   = (float*)(sm + SM_DW);
    float* parts = (float*)(sm + SM_PART);

    const int tid  = threadIdx.x;
    const int wid  = tid >> 5;
    const int lane = tid & 31;
    const int g    = lane >> 2;      // groupID (0..7)
    const int tig  = lane & 3;       // thread-in-group (0..3)
    const int b    = blockIdx.x >> 7;
    const int y    = blockIdx.x & 127;

    const float* att0 = g_att + ((b*2 + 0) << 14);
    const float* att1 = g_att + ((b*2 + 1) << 14);

    // ---- build im2col A (half) [128 px][120 k] straight from g_att ----
    {
        const int px = tid & 127;
        #pragma unroll
        for (int it = 0; it < 30; it++){
            int k = (tid >> 7) + it*4;          // 0..119
            float v = 0.f;
            if (k < NOFF){
                int c  = (k >= KK) ? 1 : 0;
                int r  = k - c*KK;
                int dy = r / 7;
                int dx = r - dy*7;
                int gy = y + dy - 3;
                int gx = px + dx - 3;
                if ((unsigned)gy < (unsigned)Hn && (unsigned)gx < (unsigned)Wn){
                    const float* src = c ? att1 : att0;
                    v = __ldg(src + (gy << 7) + gx);
                }
            }
            Ash[px*KS2 + k] = __float2half_rn(v);
        }
    }
    if (tid < NP)   biass[tid] = g_bias[tid];
    if (tid < 2*KK) dws[tid]   = dconv_w[tid];
    __syncthreads();

    // ---- warp GEMM: 16 warps = 8(M)x2(N); per pass 16(M)x40(N), K=112 ----
    const int mrow  = (wid & 7) * 16;
    const int nbase = (wid >> 3) * 80;

    #pragma unroll 1
    for (int pass = 0; pass < 2; pass++){
        const int ncolp = nbase + pass*40;
        float acc[5][4];
        #pragma unroll
        for (int ni = 0; ni < 5; ni++)
            #pragma unroll
            for (int j = 0; j < 4; j++) acc[ni][j] = 0.f;

        #pragma unroll
        for (int ks = 0; ks < 7; ks++){
            const int k0 = ks*16;
            const uint32_t a0 = *(const uint32_t*)(Ash + (mrow+g  )*KS2 + k0 + 2*tig    );
            const uint32_t a1 = *(const uint32_t*)(Ash + (mrow+8+g)*KS2 + k0 + 2*tig    );
            const uint32_t a2 = *(const uint32_t*)(Ash + (mrow+g  )*KS2 + k0 + 2*tig + 8);
            const uint32_t a3 = *(const uint32_t*)(Ash + (mrow+8+g)*KS2 + k0 + 2*tig + 8);
            #pragma unroll
            for (int ni = 0; ni < 5; ni++){
                const int n0 = ncolp + ni*8;
                const __half* bp = g_wBh + (n0+g)*KS2 + k0 + 2*tig;
                uint32_t b0 = __ldg((const uint32_t*)bp);
                uint32_t b1 = __ldg((const uint32_t*)(bp + 8));
                asm volatile(
                    "mma.sync.aligned.m16n8k16.row.col.f32.f16.f16.f32 "
                    "{%0,%1,%2,%3}, {%4,%5,%6,%7}, {%8,%9}, {%0,%1,%2,%3};"
                    : "+f"(acc[ni][0]), "+f"(acc[ni][1]),
                      "+f"(acc[ni][2]), "+f"(acc[ni][3])
                    : "r"(a0), "r"(a1), "r"(a2), "r"(a3), "r"(b0), "r"(b1));
            }
        }

        // ---- per-pass epilogue: bias + mask sigmoid -> convs[ch][px] ----
        #pragma unroll
        for (int ni = 0; ni < 5; ni++){
            const int n0 = ncolp + ni*8 + 2*tig;
            #pragma unroll
            for (int j = 0; j < 4; j++){
                int ch = n0 + (j & 1);
                int px = mrow + g + ((j >> 1) << 3);
                if (ch < NCH){
                    float v = acc[ni][j] + biass[ch];
                    if (ch >= NOFF) v = 2.f/(1.f + __expf(-v));
                    convs[ch*CS + px] = v;
                }
            }
        }
    }
    __syncthreads();

    // ---- deformable sampling: 4 ways x 128 px ----
    {
        const int way = tid >> 7;
        const int px  = tid & 127;
        float part = 0.f;
        #pragma unroll 2
        for (int kk = way; kk < KK; kk += 4){
            float oy = convs[(2*kk  )*CS + px];
            float ox = convs[(2*kk+1)*CS + px];
            float mk = convs[(NOFF+kk)*CS + px];
            float py = (float)(y + kk/7 - 3) + oy;
            float pxx= (float)(px + kk%7 - 3) + ox;
            float s0, s1;
            bilin2(att0, att1, py, pxx, s0, s1);
            part += (s0*dws[kk] + s1*dws[KK+kk]) * mk;
        }
        parts[way*128 + px] = part;
    }
    __syncthreads();

    if (tid < 128){
        float d = parts[tid] + parts[128+tid] + parts[256+tid] + parts[384+tid];
        g_attmap[(b << 14) + (y << 7) + tid] = 1.f/(1.f + __expf(-d));
    }
}

// ================= K3: out = x * attmap (streaming) =================
__global__ void dsa_mul_kernel(const float* __restrict__ x,
                               float* __restrict__ out){
    int gid = blockIdx.x * 256 + threadIdx.x;       // float4 index
    float4 xv = __ldcs((const float4*)x + gid);
    int e   = gid << 2;
    int b   = e >> 22;
    int pix = e & 16383;
    float4 a = *(const float4*)(g_attmap + (b << 14) + pix);
    xv.x *= a.x; xv.y *= a.y; xv.z *= a.z; xv.w *= a.w;
    __stcs((float4*)out + gid, xv);
}

// ================= launch =================
extern "C" void kernel_launch(void* const* d_in, const int* in_sizes, int n_in,
                              void* d_out, int out_size){
    const float* x        = (const float*)d_in[0];
    const float* offset_w = (const float*)d_in[1];
    const float* offset_b = (const float*)d_in[2];
    const float* mod_w    = (const float*)d_in[3];
    const float* mod_b    = (const float*)d_in[4];
    const float* dconv_w  = (const float*)d_in[5];
    float* out = (float*)d_out;

    cudaFuncSetAttribute(dsa_conv_deform_kernel,
                         cudaFuncAttributeMaxDynamicSharedMemorySize, SM_TOTAL);

    dsa_prep_kernel<<<16, 512>>>(offset_w, offset_b, mod_w, mod_b);
    dsa_reduce_kernel<<<128, 256>>>(x);
    dsa_conv_deform_kernel<<<Bn*Hn, 512, SM_TOTAL>>>(dconv_w);
    dsa_mul_kernel<<<(Bn*Cn*HW/4)/256, 256>>>(x, out);
}